// round 8
// baseline (speedup 1.0000x reference)
#include <cuda_runtime.h>
#include <math.h>
#include <stdint.h>

#define B     32
#define TENC  256
#define TOUT  400
#define EMB   512
#define NMEL  80
#define PN    256
#define ARNN  1024
#define DRNN  1024
#define AD    128
#define NF    32
#define KSZ   31

#define NBLK  148
#define NTHR  512
#define NWRP  (NBLK * 16)

#define ATT_TASKS  (ARNN * B)          // 32768
#define CONV_TASKS (B * TENC)          // 8192
#define DEC_TASKS  (DRNN * B)          // 32768
#define PA_ALL     (ATT_TASKS + CONV_TASKS + DEC_TASKS)
#define PROJ_TASKS ((NMEL + 1) * B)    // 2592

#define GATE_OFF  ((size_t)B * NMEL * TOUT)
#define ALIGN_OFF (GATE_OFF + (size_t)B * TOUT)

// ---------------- device scratch ----------------
__device__ __align__(16) float g_xs[(size_t)TOUT * B * PN];
__device__ __align__(16) float g_keys[(size_t)B * TENC * AD];
__device__ __align__(16) float g_loc[(size_t)B * TENC * AD];
__device__ __align__(16) float g_ah[2][B * ARNN];
__device__ __align__(16) float g_ac[B * ARNN];
__device__ __align__(16) float g_dh[2][B * DRNN];
__device__ __align__(16) float g_dc[B * DRNN];
__device__ __align__(16) float g_ctx[2][B * EMB];
__device__ __align__(16) float g_aw[B * TENC];
__device__ __align__(16) float g_awc[B * TENC];
__device__ __align__(16) float g_w1T[NMEL * PN];   // [k<80][m<256]
__device__ __align__(16) float g_w2T[PN * PN];     // [k][m]
__device__ __align__(16) float g_wkT[EMB * AD];    // [k<512][d<128]

__device__ unsigned g_cnt = 0;
__device__ volatile unsigned g_gen = 0;

// ---------------- helpers ----------------
__device__ __forceinline__ void grid_sync() {
    __syncthreads();
    if (threadIdx.x == 0) {
        __threadfence();
        unsigned gen = g_gen;
        if (atomicAdd(&g_cnt, 1u) == gridDim.x - 1u) {
            g_cnt = 0;
            __threadfence();
            g_gen = gen + 1u;
        } else {
            while (g_gen == gen) { __nanosleep(32); }
            __threadfence();
        }
    }
    __syncthreads();
}

__device__ __forceinline__ float wredsum(float v) {
#pragma unroll
    for (int o = 16; o > 0; o >>= 1) v += __shfl_xor_sync(0xffffffffu, v, o);
    return v;
}

__device__ __forceinline__ float sig_(float x) { return 1.0f / (1.0f + expf(-x)); }

// warp-cooperative dot: lanes stride float4s; w row warp-uniform, x broadcast
__device__ __forceinline__ float dot4(const float* __restrict__ w,
                                      const float* __restrict__ x,
                                      int n4, float acc, int lane) {
    const float4* w4 = (const float4*)w;
    const float4* x4 = (const float4*)x;
#pragma unroll 4
    for (int i = lane; i < n4; i += 32) {
        float4 a = w4[i];
        float4 b = x4[i];
        acc = fmaf(a.x, b.x, acc);
        acc = fmaf(a.y, b.y, acc);
        acc = fmaf(a.z, b.z, acc);
        acc = fmaf(a.w, b.w, acc);
    }
    return acc;
}

// ---------------- params ----------------
struct Params {
    const float* memory;       // (B,TENC,EMB)
    const float* dec_inputs;   // (B,TOUT,NMEL)
    const int*   mlen;         // (B,)
    const float* att_wih;      // (4096,768)
    const float* att_whh;      // (4096,1024)
    const float* att_bih;
    const float* att_bhh;
    const float* wq;           // (128,1024)
    const float* conv_w;       // (32,2,31)
    const float* conv_b;       // (32,)
    const float* wloc;         // (128,32)
    const float* wv;           // (1,128)
    const float* dec_wih;      // (4096,1536)
    const float* dec_whh;      // (4096,1024)
    const float* dec_bih;
    const float* dec_bhh;
    const float* wproj;        // (80,1536)
    const float* bproj;        // (80,)
    const float* wgate;        // (1,1536)
    const float* bgate;        // (1,)
    float*       out;
};

// ---------------- pre-kernels ----------------
__global__ void k_trans_w1(const float* __restrict__ w) {   // (256,80) -> [k][m]
    int i = blockIdx.x * blockDim.x + threadIdx.x;
    if (i < PN * NMEL) { int r = i / NMEL, c = i % NMEL; g_w1T[c * PN + r] = w[i]; }
}
__global__ void k_trans_w2(const float* __restrict__ w) {   // (256,256)
    int i = blockIdx.x * blockDim.x + threadIdx.x;
    if (i < PN * PN) { int r = i / PN, c = i % PN; g_w2T[c * PN + r] = w[i]; }
}
__global__ void k_trans_wk(const float* __restrict__ w) {   // (128,512) -> [k][d]
    int i = blockIdx.x * blockDim.x + threadIdx.x;
    if (i < AD * EMB) { int r = i / EMB, c = i % EMB; g_wkT[c * AD + r] = w[i]; }
}

// prenet for one timestep t per block: 256 threads, thread m covers all 32 b
__global__ __launch_bounds__(256) void k_prenet(const float* __restrict__ dec_inputs) {
    __shared__ float sin_[B][NMEL];
    __shared__ float sh1[B][PN];
    int t = blockIdx.x;
    int tid = threadIdx.x;
    for (int i = tid; i < B * NMEL; i += 256) {
        int b = i / NMEL, k = i % NMEL;
        sin_[b][k] = (t == 0) ? 0.0f
                   : dec_inputs[((size_t)b * TOUT + (t - 1)) * NMEL + k];
    }
    __syncthreads();
    int m = tid;
    float acc[B];
#pragma unroll
    for (int b = 0; b < B; ++b) acc[b] = 0.0f;
    for (int k = 0; k < NMEL; ++k) {
        float wv_ = g_w1T[k * PN + m];
#pragma unroll
        for (int b = 0; b < B; ++b) acc[b] = fmaf(wv_, sin_[b][k], acc[b]);
    }
#pragma unroll
    for (int b = 0; b < B; ++b) sh1[b][m] = fmaxf(acc[b], 0.0f);
    __syncthreads();
#pragma unroll
    for (int b = 0; b < B; ++b) acc[b] = 0.0f;
    for (int k = 0; k < PN; ++k) {
        float wv_ = g_w2T[k * PN + m];
#pragma unroll
        for (int b = 0; b < B; ++b) acc[b] = fmaf(wv_, sh1[b][k], acc[b]);
    }
#pragma unroll
    for (int b = 0; b < B; ++b)
        g_xs[((size_t)t * B + b) * PN + m] = fmaxf(acc[b], 0.0f);
}

// keys: block = (b, group of 8 t); 128 threads (thread = d)
__global__ __launch_bounds__(128) void k_keys(const float* __restrict__ memory) {
    __shared__ float sm[8][EMB];
    int b  = blockIdx.x >> 5;
    int t0 = (blockIdx.x & 31) * 8;
    int tid = threadIdx.x;
    for (int i = tid; i < 8 * EMB; i += 128) {
        int j = i >> 9, k = i & 511;
        sm[j][k] = memory[((size_t)b * TENC + t0 + j) * EMB + k];
    }
    __syncthreads();
    int d = tid;
    float acc[8];
#pragma unroll
    for (int j = 0; j < 8; ++j) acc[j] = 0.0f;
    for (int k = 0; k < EMB; ++k) {
        float wv_ = g_wkT[k * AD + d];
#pragma unroll
        for (int j = 0; j < 8; ++j) acc[j] = fmaf(wv_, sm[j][k], acc[j]);
    }
#pragma unroll
    for (int j = 0; j < 8; ++j)
        g_keys[((size_t)b * TENC + t0 + j) * AD + d] = acc[j];
}

// ---------------- persistent decoder ----------------
__global__ __launch_bounds__(NTHR) void k_decoder(Params p) {
    __shared__ float sq[AD];
    __shared__ float se[TENC];
    __shared__ float sw_[TENC];
    __shared__ float sred[2];

    const int tid  = threadIdx.x;
    const int lane = tid & 31;
    const int warp = tid >> 5;
    const int gw   = blockIdx.x * 16 + warp;

    // ---- zero-init state (deterministic per launch) ----
    {
        const int tot = blockDim.x * gridDim.x;
        const int gt  = blockIdx.x * blockDim.x + tid;
        for (int i = gt; i < 2 * B * ARNN; i += tot) { g_ah[0][i] = 0.f; }  // covers g_ah[0..1] contiguously
        for (int i = gt; i < B * ARNN; i += tot) g_ac[i] = 0.f;
        for (int i = gt; i < 2 * B * DRNN; i += tot) { g_dh[0][i] = 0.f; }
        for (int i = gt; i < B * DRNN; i += tot) g_dc[i] = 0.f;
        for (int i = gt; i < 2 * B * EMB; i += tot) { g_ctx[0][i] = 0.f; }
        for (int i = gt; i < B * TENC; i += tot) { g_aw[i] = 0.f; g_awc[i] = 0.f; }
    }
    grid_sync();

    for (int t = 0; t <= TOUT; ++t) {
        const int rp = (t + 1) & 1;   // "previous" parity
        const int wp = t & 1;         // "current" parity
        const float* ah_rd  = g_ah[rp];   // ah(t-1)
        float*       ah_wr  = g_ah[wp];   // ah(t)
        const float* dh_rd  = g_dh[wp];   // dh(t-2)
        float*       dh_wr  = g_dh[rp];   // dh(t-1)
        const float* ctx_rd = g_ctx[rp];  // ctx(t-1)
        float*       ctx_wr = g_ctx[wp];  // ctx(t)

        // ================= Phase A =================
        {
            int base = (t == TOUT) ? (ATT_TASKS + CONV_TASKS) : 0;
            int n;
            if (t == 0)         n = ATT_TASKS + CONV_TASKS;
            else if (t == TOUT) n = DEC_TASKS;
            else                n = PA_ALL;

            for (int id0 = gw; id0 < n; id0 += NWRP) {
                int id = id0 + base;
                if (id < ATT_TASKS) {
                    // ---- attention LSTM, unit u batch b ----
                    int u = id >> 5, b = id & 31;
                    const float* xrow = g_xs + ((size_t)t * B + b) * PN;
                    const float* crow = ctx_rd + b * EMB;
                    const float* hrow = ah_rd + b * ARNN;
                    float acc[4];
#pragma unroll
                    for (int g = 0; g < 4; ++g) {
                        const float* wi = p.att_wih + (size_t)((g << 10) + u) * (PN + EMB);
                        const float* wh = p.att_whh + (size_t)((g << 10) + u) * ARNN;
                        float a = 0.f;
                        a = dot4(wi, xrow, PN / 4, a, lane);
                        a = dot4(wi + PN, crow, EMB / 4, a, lane);
                        a = dot4(wh, hrow, ARNN / 4, a, lane);
                        acc[g] = wredsum(a);
                    }
                    if (lane == 0) {
                        float gi = acc[0] + p.att_bih[u]          + p.att_bhh[u];
                        float gf = acc[1] + p.att_bih[1024 + u]   + p.att_bhh[1024 + u];
                        float gg = acc[2] + p.att_bih[2048 + u]   + p.att_bhh[2048 + u];
                        float go = acc[3] + p.att_bih[3072 + u]   + p.att_bhh[3072 + u];
                        float c2 = sig_(gf) * g_ac[b * ARNN + u] + sig_(gi) * tanhf(gg);
                        g_ac[b * ARNN + u] = c2;
                        ah_wr[b * ARNN + u] = sig_(go) * tanhf(c2);
                    }
                } else if (id < ATT_TASKS + CONV_TASKS) {
                    // ---- location conv + wloc projection, (b, tt), lane = filter ----
                    int cid = id - ATT_TASKS;
                    int b = cid >> 8, tt = cid & 255;
                    const float* cw0 = p.conv_w + lane * (2 * KSZ);
                    float cv = p.conv_b[lane];
#pragma unroll
                    for (int k = 0; k < KSZ; ++k) {
                        int pp = tt + k - 15;
                        if (pp >= 0 && pp < TENC) {
                            cv = fmaf(cw0[k],        g_aw[b * TENC + pp], cv);
                            cv = fmaf(cw0[KSZ + k],  g_awc[b * TENC + pp], cv);
                        }
                    }
                    float a0 = 0.f, a1 = 0.f, a2 = 0.f, a3 = 0.f;
#pragma unroll
                    for (int src = 0; src < 32; ++src) {
                        float v = __shfl_sync(0xffffffffu, cv, src);
                        a0 = fmaf(v, p.wloc[(lane)       * NF + src], a0);
                        a1 = fmaf(v, p.wloc[(lane + 32)  * NF + src], a1);
                        a2 = fmaf(v, p.wloc[(lane + 64)  * NF + src], a2);
                        a3 = fmaf(v, p.wloc[(lane + 96)  * NF + src], a3);
                    }
                    size_t o = ((size_t)b * TENC + tt) * AD;
                    g_loc[o + lane]      = a0;
                    g_loc[o + lane + 32] = a1;
                    g_loc[o + lane + 64] = a2;
                    g_loc[o + lane + 96] = a3;
                } else {
                    // ---- decoder LSTM for step t-1, unit u batch b ----
                    int did = id - (ATT_TASKS + CONV_TASKS);
                    int u = did >> 5, b = did & 31;
                    const float* arow = ah_rd + b * ARNN;   // ah(t-1)
                    const float* crow = ctx_rd + b * EMB;   // ctx(t-1)
                    const float* hrow = dh_rd + b * DRNN;   // dh(t-2)
                    float acc[4];
#pragma unroll
                    for (int g = 0; g < 4; ++g) {
                        const float* wi = p.dec_wih + (size_t)((g << 10) + u) * (ARNN + EMB);
                        const float* wh = p.dec_whh + (size_t)((g << 10) + u) * DRNN;
                        float a = 0.f;
                        a = dot4(wi, arow, ARNN / 4, a, lane);
                        a = dot4(wi + ARNN, crow, EMB / 4, a, lane);
                        a = dot4(wh, hrow, DRNN / 4, a, lane);
                        acc[g] = wredsum(a);
                    }
                    if (lane == 0) {
                        float gi = acc[0] + p.dec_bih[u]        + p.dec_bhh[u];
                        float gf = acc[1] + p.dec_bih[1024 + u] + p.dec_bhh[1024 + u];
                        float gg = acc[2] + p.dec_bih[2048 + u] + p.dec_bhh[2048 + u];
                        float go = acc[3] + p.dec_bih[3072 + u] + p.dec_bhh[3072 + u];
                        float c2 = sig_(gf) * g_dc[b * DRNN + u] + sig_(gi) * tanhf(gg);
                        g_dc[b * DRNN + u] = c2;
                        dh_wr[b * DRNN + u] = sig_(go) * tanhf(c2);
                    }
                }
            }
        }
        grid_sync();

        // ================= Phase B =================
        if (blockIdx.x < B) {
            if (t < TOUT) {
                const int b = blockIdx.x;
                // q = ah(t) @ wq^T : warp w -> d in [8w, 8w+8)
                const float* hrow = ah_wr + b * ARNN;   // ah(t)
#pragma unroll
                for (int j = 0; j < 8; ++j) {
                    int d = warp * 8 + j;
                    float a = dot4(p.wq + (size_t)d * ARNN, hrow, ARNN / 4, 0.f, lane);
                    a = wredsum(a);
                    if (lane == 0) sq[d] = a;
                }
                __syncthreads();
                // energies
                const int len = p.mlen[b];
#pragma unroll
                for (int j = 0; j < 16; ++j) {
                    int tt = warp + j * 16;
                    size_t o = ((size_t)b * TENC + tt) * AD;
                    float a = 0.f;
#pragma unroll
                    for (int jj = 0; jj < 4; ++jj) {
                        int d = lane + jj * 32;
                        float s = sq[d] + g_keys[o + d] + g_loc[o + d];
                        a = fmaf(p.wv[d], tanhf(s), a);
                    }
                    a = wredsum(a);
                    if (lane == 0) se[tt] = (tt >= len) ? -1e9f : a;
                }
                __syncthreads();
                // softmax stats (warp 0)
                if (warp == 0) {
                    float m = -3.4e38f;
#pragma unroll
                    for (int j = 0; j < 8; ++j) m = fmaxf(m, se[lane + j * 32]);
#pragma unroll
                    for (int o = 16; o > 0; o >>= 1)
                        m = fmaxf(m, __shfl_xor_sync(0xffffffffu, m, o));
                    float s = 0.f;
#pragma unroll
                    for (int j = 0; j < 8; ++j) s += expf(se[lane + j * 32] - m);
                    s = wredsum(s);
                    if (lane == 0) { sred[0] = m; sred[1] = 1.0f / s; }
                }
                __syncthreads();
                if (tid < TENC) {
                    float w = expf(se[tid] - sred[0]) * sred[1];
                    sw_[tid] = w;
                    g_aw[b * TENC + tid] = w;
                    g_awc[b * TENC + tid] += w;
                    p.out[ALIGN_OFF + ((size_t)b * TOUT + t) * TENC + tid] = w;
                }
                __syncthreads();
                // ctx(t): warp w handles e in [32w, 32w+32)
                {
                    int e = warp * 32 + lane;
                    const float* mb = p.memory + (size_t)b * TENC * EMB + e;
                    float acc = 0.f;
#pragma unroll 8
                    for (int tt = 0; tt < TENC; ++tt)
                        acc = fmaf(sw_[tt], mb[(size_t)tt * EMB], acc);
                    ctx_wr[b * EMB + e] = acc;
                }
            }
        } else if (t > 0) {
            // projection for step t-1: warps of blocks 32..147
            int pgw = (blockIdx.x - B) * 16 + warp;
            for (int id = pgw; id < PROJ_TASKS; id += (NBLK - B) * 16) {
                int row = id >> 5, b = id & 31;
                const float* hrow = dh_wr + b * DRNN;    // dh(t-1)
                const float* crow = ctx_rd + b * EMB;    // ctx(t-1)
                const float* wr; float bias;
                if (row < NMEL) { wr = p.wproj + (size_t)row * (DRNN + EMB); bias = p.bproj[row]; }
                else            { wr = p.wgate;                               bias = p.bgate[0]; }
                float a = 0.f;
                a = dot4(wr, hrow, DRNN / 4, a, lane);
                a = dot4(wr + DRNN, crow, EMB / 4, a, lane);
                a = wredsum(a) + bias;
                if (lane == 0) {
                    if (row < NMEL)
                        p.out[((size_t)b * NMEL + row) * TOUT + (t - 1)] = a;
                    else
                        p.out[GATE_OFF + (size_t)b * TOUT + (t - 1)] = a;
                }
            }
        }
        grid_sync();
    }
}

// ---------------- launch ----------------
extern "C" void kernel_launch(void* const* d_in, const int* in_sizes, int n_in,
                              void* d_out, int out_size) {
    Params p;
    p.memory     = (const float*)d_in[0];
    p.dec_inputs = (const float*)d_in[1];
    p.mlen       = (const int*)  d_in[2];
    const float* prenet_w1 = (const float*)d_in[3];
    const float* prenet_w2 = (const float*)d_in[4];
    p.att_wih    = (const float*)d_in[5];
    p.att_whh    = (const float*)d_in[6];
    p.att_bih    = (const float*)d_in[7];
    p.att_bhh    = (const float*)d_in[8];
    p.wq         = (const float*)d_in[9];
    const float* wk = (const float*)d_in[10];
    p.conv_w     = (const float*)d_in[11];
    p.conv_b     = (const float*)d_in[12];
    p.wloc       = (const float*)d_in[13];
    p.wv         = (const float*)d_in[14];
    p.dec_wih    = (const float*)d_in[15];
    p.dec_whh    = (const float*)d_in[16];
    p.dec_bih    = (const float*)d_in[17];
    p.dec_bhh    = (const float*)d_in[18];
    p.wproj      = (const float*)d_in[19];
    p.bproj      = (const float*)d_in[20];
    p.wgate      = (const float*)d_in[21];
    p.bgate      = (const float*)d_in[22];
    p.out        = (float*)d_out;

    k_trans_w1<<<(PN * NMEL + 255) / 256, 256>>>(prenet_w1);
    k_trans_w2<<<(PN * PN + 255) / 256, 256>>>(prenet_w2);
    k_trans_wk<<<(AD * EMB + 255) / 256, 256>>>(wk);
    k_prenet<<<TOUT, 256>>>(p.dec_inputs);
    k_keys<<<B * (TENC / 8), 128>>>(p.memory);
    k_decoder<<<NBLK, NTHR>>>(p);
}

// round 12
// speedup vs baseline: 1.0577x; 1.0577x over previous
#include <cuda_runtime.h>
#include <math.h>
#include <stdint.h>

#define B     32
#define TENC  256
#define TOUT  400
#define EMB   512
#define NMEL  80
#define PN    256
#define ARNN  1024
#define DRNN  1024
#define AD    128
#define NF    32
#define KSZ   31

#define KA    1792   // att GEMM depth: 256 x + 512 ctx + 1024 ah
#define KD    2560   // dec GEMM depth: 1024 ah + 512 ctx + 1024 dh

#define NBLK  148
#define NTHR  512

#define GATE_OFF  ((size_t)B * NMEL * TOUT)
#define ALIGN_OFF (GATE_OFF + (size_t)B * TOUT)

// ---------------- device scratch ----------------
__device__ __align__(16) float g_xsT[(size_t)TOUT * PN * B];   // [t][k][b]
__device__ __align__(16) float g_keys[(size_t)B * TENC * AD];
__device__ __align__(16) float g_loc[(size_t)B * TENC * AD];
__device__ __align__(16) float g_ahT[2][ARNN * B];   // [u][b]
__device__ __align__(16) float g_ahP[2][B * ARNN];   // [b][u] for q
__device__ __align__(16) float g_acT[ARNN * B];
__device__ __align__(16) float g_dhT[2][DRNN * B];
__device__ __align__(16) float g_dcT[DRNN * B];
__device__ __align__(16) float g_ctxT[2][EMB * B];   // [e][b]
__device__ __align__(16) float g_aw[B * TENC];
__device__ __align__(16) float g_awc[B * TENC];
__device__ __align__(16) float g_wQa[(size_t)ARNN * KA * 4];  // [u][k][g] 29MB
__device__ __align__(16) float g_wQd[(size_t)DRNN * KD * 4];  // 42MB
__device__ __align__(16) float g_bqa[ARNN * 4];
__device__ __align__(16) float g_bqd[DRNN * 4];
__device__ __align__(16) float g_w1T[NMEL * PN];
__device__ __align__(16) float g_w2T[PN * PN];
__device__ __align__(16) float g_wkT[EMB * AD];

__device__ unsigned g_cnt = 0;
__device__ volatile unsigned g_gen = 0;

// ---------------- f32x2 helpers ----------------
typedef unsigned long long ull;

__device__ __forceinline__ ull pack2(float x, float y) {
    ull r; asm("mov.b64 %0,{%1,%2};" : "=l"(r) : "f"(x), "f"(y)); return r;
}
__device__ __forceinline__ void fma2(ull& d, ull a, ull b) {
    asm("fma.rn.f32x2 %0,%1,%2,%0;" : "+l"(d) : "l"(a), "l"(b));
}
__device__ __forceinline__ float2 unpack2(ull a) {
    float2 r; asm("mov.b64 {%0,%1},%2;" : "=f"(r.x), "=f"(r.y) : "l"(a)); return r;
}

// ---------------- misc helpers ----------------
__device__ __forceinline__ void grid_sync() {
    __syncthreads();
    if (threadIdx.x == 0) {
        __threadfence();
        unsigned gen = g_gen;
        if (atomicAdd(&g_cnt, 1u) == gridDim.x - 1u) {
            g_cnt = 0;
            __threadfence();
            g_gen = gen + 1u;
        } else {
            while (g_gen == gen) { __nanosleep(32); }
            __threadfence();
        }
    }
    __syncthreads();
}

__device__ __forceinline__ float wredsum(float v) {
#pragma unroll
    for (int o = 16; o > 0; o >>= 1) v += __shfl_xor_sync(0xffffffffu, v, o);
    return v;
}

__device__ __forceinline__ float sig_(float x) { return 1.0f / (1.0f + expf(-x)); }

__device__ __forceinline__ float dot4(const float* __restrict__ w,
                                      const float* __restrict__ x,
                                      int n4, float acc, int lane) {
    const float4* w4 = (const float4*)w;
    const float4* x4 = (const float4*)x;
#pragma unroll 4
    for (int i = lane; i < n4; i += 32) {
        float4 a = w4[i];
        float4 b = x4[i];
        acc = fmaf(a.x, b.x, acc);
        acc = fmaf(a.y, b.y, acc);
        acc = fmaf(a.z, b.z, acc);
        acc = fmaf(a.w, b.w, acc);
    }
    return acc;
}

// GEMM segment: 2 units, 4 gates each, 32 batches (2/lane via f32x2).
__device__ __forceinline__ void gemm_seg(const float* __restrict__ act,
                                         const ulonglong2* __restrict__ w0,
                                         const ulonglong2* __restrict__ w1,
                                         int n, int lane,
                                         ull& a00, ull& a01, ull& a10, ull& a11) {
#pragma unroll 8
    for (int k = 0; k < n; ++k) {
        float a = act[k * 32 + lane];
        ull a2 = pack2(a, a);
        ulonglong2 wa = w0[k];
        ulonglong2 wb = w1[k];
        fma2(a00, wa.x, a2);
        fma2(a01, wa.y, a2);
        fma2(a10, wb.x, a2);
        fma2(a11, wb.y, a2);
    }
}

// ---------------- params ----------------
struct Params {
    const float* memory;
    const float* dec_inputs;
    const int*   mlen;
    const float* att_wih;  const float* att_whh;
    const float* att_bih;  const float* att_bhh;
    const float* wq;
    const float* conv_w;   const float* conv_b;
    const float* wloc;     const float* wv;
    const float* dec_wih;  const float* dec_whh;
    const float* dec_bih;  const float* dec_bhh;
    const float* wproj;    const float* bproj;
    const float* wgate;    const float* bgate;
    float*       out;
};

// ---------------- pre-kernels ----------------
__global__ void k_trans_w1(const float* __restrict__ w) {
    int i = blockIdx.x * blockDim.x + threadIdx.x;
    if (i < PN * NMEL) { int r = i / NMEL, c = i % NMEL; g_w1T[c * PN + r] = w[i]; }
}
__global__ void k_trans_w2(const float* __restrict__ w) {
    int i = blockIdx.x * blockDim.x + threadIdx.x;
    if (i < PN * PN) { int r = i / PN, c = i % PN; g_w2T[c * PN + r] = w[i]; }
}
__global__ void k_trans_wk(const float* __restrict__ w) {
    int i = blockIdx.x * blockDim.x + threadIdx.x;
    if (i < AD * EMB) { int r = i / EMB, c = i % EMB; g_wkT[c * AD + r] = w[i]; }
}

// weight quad transpose: wQ[u][k][g] from wih(rows g*1024+u, len Ki) ++ whh(len H)
__global__ void k_quad_att(const float* __restrict__ wih, const float* __restrict__ whh) {
    for (size_t i = blockIdx.x * (size_t)blockDim.x + threadIdx.x;
         i < (size_t)ARNN * KA; i += (size_t)gridDim.x * blockDim.x) {
        int u = (int)(i / KA), k = (int)(i % KA);
        float4 v;
        if (k < PN + EMB) {
            v.x = wih[((size_t)(0 * ARNN + u)) * (PN + EMB) + k];
            v.y = wih[((size_t)(1 * ARNN + u)) * (PN + EMB) + k];
            v.z = wih[((size_t)(2 * ARNN + u)) * (PN + EMB) + k];
            v.w = wih[((size_t)(3 * ARNN + u)) * (PN + EMB) + k];
        } else {
            int kk = k - (PN + EMB);
            v.x = whh[((size_t)(0 * ARNN + u)) * ARNN + kk];
            v.y = whh[((size_t)(1 * ARNN + u)) * ARNN + kk];
            v.z = whh[((size_t)(2 * ARNN + u)) * ARNN + kk];
            v.w = whh[((size_t)(3 * ARNN + u)) * ARNN + kk];
        }
        ((float4*)g_wQa)[i] = v;
    }
}
__global__ void k_quad_dec(const float* __restrict__ wih, const float* __restrict__ whh) {
    for (size_t i = blockIdx.x * (size_t)blockDim.x + threadIdx.x;
         i < (size_t)DRNN * KD; i += (size_t)gridDim.x * blockDim.x) {
        int u = (int)(i / KD), k = (int)(i % KD);
        float4 v;
        if (k < ARNN + EMB) {
            v.x = wih[((size_t)(0 * DRNN + u)) * (ARNN + EMB) + k];
            v.y = wih[((size_t)(1 * DRNN + u)) * (ARNN + EMB) + k];
            v.z = wih[((size_t)(2 * DRNN + u)) * (ARNN + EMB) + k];
            v.w = wih[((size_t)(3 * DRNN + u)) * (ARNN + EMB) + k];
        } else {
            int kk = k - (ARNN + EMB);
            v.x = whh[((size_t)(0 * DRNN + u)) * DRNN + kk];
            v.y = whh[((size_t)(1 * DRNN + u)) * DRNN + kk];
            v.z = whh[((size_t)(2 * DRNN + u)) * DRNN + kk];
            v.w = whh[((size_t)(3 * DRNN + u)) * DRNN + kk];
        }
        ((float4*)g_wQd)[i] = v;
    }
}
__global__ void k_bias(const float* abih, const float* abhh,
                       const float* dbih, const float* dbhh) {
    int i = blockIdx.x * blockDim.x + threadIdx.x;
    if (i < ARNN) {
#pragma unroll
        for (int g = 0; g < 4; ++g)
            g_bqa[i * 4 + g] = abih[g * ARNN + i] + abhh[g * ARNN + i];
    } else if (i < 2 * ARNN) {
        int u = i - ARNN;
#pragma unroll
        for (int g = 0; g < 4; ++g)
            g_bqd[u * 4 + g] = dbih[g * DRNN + u] + dbhh[g * DRNN + u];
    }
}

// prenet for one timestep t per block; writes transposed [t][k][b]
__global__ __launch_bounds__(256) void k_prenet(const float* __restrict__ dec_inputs) {
    __shared__ float sin_[B][NMEL];
    __shared__ float sh1[B][PN];
    int t = blockIdx.x;
    int tid = threadIdx.x;
    for (int i = tid; i < B * NMEL; i += 256) {
        int b = i / NMEL, k = i % NMEL;
        sin_[b][k] = (t == 0) ? 0.0f
                   : dec_inputs[((size_t)b * TOUT + (t - 1)) * NMEL + k];
    }
    __syncthreads();
    int m = tid;
    float acc[B];
#pragma unroll
    for (int b = 0; b < B; ++b) acc[b] = 0.0f;
    for (int k = 0; k < NMEL; ++k) {
        float wv_ = g_w1T[k * PN + m];
#pragma unroll
        for (int b = 0; b < B; ++b) acc[b] = fmaf(wv_, sin_[b][k], acc[b]);
    }
#pragma unroll
    for (int b = 0; b < B; ++b) sh1[b][m] = fmaxf(acc[b], 0.0f);
    __syncthreads();
#pragma unroll
    for (int b = 0; b < B; ++b) acc[b] = 0.0f;
    for (int k = 0; k < PN; ++k) {
        float wv_ = g_w2T[k * PN + m];
#pragma unroll
        for (int b = 0; b < B; ++b) acc[b] = fmaf(wv_, sh1[b][k], acc[b]);
    }
#pragma unroll
    for (int b = 0; b < B; ++b)
        g_xsT[((size_t)t * PN + m) * B + b] = fmaxf(acc[b], 0.0f);
}

__global__ __launch_bounds__(128) void k_keys(const float* __restrict__ memory) {
    __shared__ float sm[8][EMB];
    int b  = blockIdx.x >> 5;
    int t0 = (blockIdx.x & 31) * 8;
    int tid = threadIdx.x;
    for (int i = tid; i < 8 * EMB; i += 128) {
        int j = i >> 9, k = i & 511;
        sm[j][k] = memory[((size_t)b * TENC + t0 + j) * EMB + k];
    }
    __syncthreads();
    int d = tid;
    float acc[8];
#pragma unroll
    for (int j = 0; j < 8; ++j) acc[j] = 0.0f;
    for (int k = 0; k < EMB; ++k) {
        float wv_ = g_wkT[k * AD + d];
#pragma unroll
        for (int j = 0; j < 8; ++j) acc[j] = fmaf(wv_, sm[j][k], acc[j]);
    }
#pragma unroll
    for (int j = 0; j < 8; ++j)
        g_keys[((size_t)b * TENC + t0 + j) * AD + d] = acc[j];
}

// ---------------- persistent decoder ----------------
__global__ __launch_bounds__(NTHR) void k_decoder(Params p) {
    __shared__ float sq[AD];
    __shared__ float se[TENC];
    __shared__ float sw_[TENC];
    __shared__ float sred[2];

    const int tid  = threadIdx.x;
    const int lane = tid & 31;
    const int warp = tid >> 5;

    // ---- zero-init state ----
    {
        const int tot = blockDim.x * gridDim.x;
        const int gt  = blockIdx.x * blockDim.x + tid;
        for (int i = gt; i < 2 * ARNN * B; i += tot) { g_ahT[0][i] = 0.f; g_ahP[0][i] = 0.f; }
        for (int i = gt; i < 2 * DRNN * B; i += tot) g_dhT[0][i] = 0.f;
        for (int i = gt; i < 2 * EMB * B; i += tot) g_ctxT[0][i] = 0.f;
        for (int i = gt; i < ARNN * B; i += tot) g_acT[i] = 0.f;
        for (int i = gt; i < DRNN * B; i += tot) g_dcT[i] = 0.f;
        for (int i = gt; i < B * TENC; i += tot) { g_aw[i] = 0.f; g_awc[i] = 0.f; }
    }
    grid_sync();

    for (int t = 0; t <= TOUT; ++t) {
        const int rp = (t + 1) & 1;
        const int wp = t & 1;

        // ================= Phase A =================
        if (warp < 7) {
            int id = blockIdx.x * 7 + warp;     // att/dec interleaved per SM
            if (id < 1024) {
                int which = id & 1, ug = id >> 1;
                if (which == 0 && t < TOUT) {
                    // ---- attention LSTM(t): units 2ug, 2ug+1 ----
                    int u0 = ug * 2;
                    const ulonglong2* w0 = (const ulonglong2*)g_wQa + (size_t)u0 * KA;
                    const ulonglong2* w1 = w0 + KA;
                    ull a00 = 0, a01 = 0, a10 = 0, a11 = 0;
                    gemm_seg(g_xsT + (size_t)t * PN * B, w0, w1, PN, lane, a00, a01, a10, a11);
                    gemm_seg(g_ctxT[rp], w0 + PN, w1 + PN, EMB, lane, a00, a01, a10, a11);
                    gemm_seg(g_ahT[rp], w0 + PN + EMB, w1 + PN + EMB, ARNN, lane, a00, a01, a10, a11);
#pragma unroll
                    for (int j = 0; j < 2; ++j) {
                        int u = u0 + j;
                        float2 g01 = unpack2(j ? a10 : a00);
                        float2 g23 = unpack2(j ? a11 : a01);
                        float4 bb = ((const float4*)g_bqa)[u];
                        float i_ = g01.x + bb.x, f_ = g01.y + bb.y;
                        float gg = g23.x + bb.z, oo = g23.y + bb.w;
                        float c  = g_acT[u * 32 + lane];
                        float c2 = sig_(f_) * c + sig_(i_) * tanhf(gg);
                        g_acT[u * 32 + lane] = c2;
                        float h = sig_(oo) * tanhf(c2);
                        g_ahT[wp][u * 32 + lane] = h;
                        g_ahP[wp][lane * ARNN + u] = h;
                    }
                } else if (which == 1 && t > 0) {
                    // ---- decoder LSTM(t-1): units 2ug, 2ug+1 ----
                    int u0 = ug * 2;
                    const ulonglong2* w0 = (const ulonglong2*)g_wQd + (size_t)u0 * KD;
                    const ulonglong2* w1 = w0 + KD;
                    ull a00 = 0, a01 = 0, a10 = 0, a11 = 0;
                    gemm_seg(g_ahT[rp], w0, w1, ARNN, lane, a00, a01, a10, a11);
                    gemm_seg(g_ctxT[rp], w0 + ARNN, w1 + ARNN, EMB, lane, a00, a01, a10, a11);
                    gemm_seg(g_dhT[wp], w0 + ARNN + EMB, w1 + ARNN + EMB, DRNN, lane, a00, a01, a10, a11);
#pragma unroll
                    for (int j = 0; j < 2; ++j) {
                        int u = u0 + j;
                        float2 g01 = unpack2(j ? a10 : a00);
                        float2 g23 = unpack2(j ? a11 : a01);
                        float4 bb = ((const float4*)g_bqd)[u];
                        float i_ = g01.x + bb.x, f_ = g01.y + bb.y;
                        float gg = g23.x + bb.z, oo = g23.y + bb.w;
                        float c  = g_dcT[u * 32 + lane];
                        float c2 = sig_(f_) * c + sig_(i_) * tanhf(gg);
                        g_dcT[u * 32 + lane] = c2;
                        g_dhT[rp][u * 32 + lane] = sig_(oo) * tanhf(c2);
                    }
                }
            }
        } else if (t < TOUT) {
            // ---- location conv + wloc projection ----
            for (int c = blockIdx.x * 9 + (warp - 7); c < B * TENC; c += NBLK * 9) {
                int b = c >> 8, tt = c & 255;
                const float* cw0 = p.conv_w + lane * (2 * KSZ);
                float cv = p.conv_b[lane];
#pragma unroll
                for (int k = 0; k < KSZ; ++k) {
                    int pp = tt + k - 15;
                    if (pp >= 0 && pp < TENC) {
                        cv = fmaf(cw0[k],       g_aw[b * TENC + pp], cv);
                        cv = fmaf(cw0[KSZ + k], g_awc[b * TENC + pp], cv);
                    }
                }
                float a0 = 0.f, a1 = 0.f, a2 = 0.f, a3 = 0.f;
#pragma unroll
                for (int src = 0; src < 32; ++src) {
                    float v = __shfl_sync(0xffffffffu, cv, src);
                    a0 = fmaf(v, p.wloc[(lane)      * NF + src], a0);
                    a1 = fmaf(v, p.wloc[(lane + 32) * NF + src], a1);
                    a2 = fmaf(v, p.wloc[(lane + 64) * NF + src], a2);
                    a3 = fmaf(v, p.wloc[(lane + 96) * NF + src], a3);
                }
                size_t o = ((size_t)b * TENC + tt) * AD;
                g_loc[o + lane]      = a0;
                g_loc[o + lane + 32] = a1;
                g_loc[o + lane + 64] = a2;
                g_loc[o + lane + 96] = a3;
            }
        }
        grid_sync();

        // ================= Phase B =================
        if (blockIdx.x < B) {
            if (t < TOUT) {
                const int b = blockIdx.x;
                const float* hrow = g_ahP[wp] + b * ARNN;   // ah(t)
#pragma unroll
                for (int j = 0; j < 8; ++j) {
                    int d = warp * 8 + j;
                    float a = dot4(p.wq + (size_t)d * ARNN, hrow, ARNN / 4, 0.f, lane);
                    a = wredsum(a);
                    if (lane == 0) sq[d] = a;
                }
                __syncthreads();
                const int len = p.mlen[b];
#pragma unroll
                for (int j = 0; j < 16; ++j) {
                    int tt = warp + j * 16;
                    size_t o = ((size_t)b * TENC + tt) * AD;
                    float a = 0.f;
#pragma unroll
                    for (int jj = 0; jj < 4; ++jj) {
                        int d = lane + jj * 32;
                        float s = sq[d] + g_keys[o + d] + g_loc[o + d];
                        a = fmaf(p.wv[d], tanhf(s), a);
                    }
                    a = wredsum(a);
                    if (lane == 0) se[tt] = (tt >= len) ? -1e9f : a;
                }
                __syncthreads();
                if (warp == 0) {
                    float m = -3.4e38f;
#pragma unroll
                    for (int j = 0; j < 8; ++j) m = fmaxf(m, se[lane + j * 32]);
#pragma unroll
                    for (int o = 16; o > 0; o >>= 1)
                        m = fmaxf(m, __shfl_xor_sync(0xffffffffu, m, o));
                    float s = 0.f;
#pragma unroll
                    for (int j = 0; j < 8; ++j) s += expf(se[lane + j * 32] - m);
                    s = wredsum(s);
                    if (lane == 0) { sred[0] = m; sred[1] = 1.0f / s; }
                }
                __syncthreads();
                if (tid < TENC) {
                    float w = expf(se[tid] - sred[0]) * sred[1];
                    sw_[tid] = w;
                    g_aw[b * TENC + tid] = w;
                    g_awc[b * TENC + tid] += w;
                    p.out[ALIGN_OFF + ((size_t)b * TOUT + t) * TENC + tid] = w;
                }
                __syncthreads();
                {
                    int e = warp * 32 + lane;
                    const float* mb = p.memory + (size_t)b * TENC * EMB + e;
                    float acc = 0.f;
#pragma unroll 8
                    for (int tt = 0; tt < TENC; ++tt)
                        acc = fmaf(sw_[tt], mb[(size_t)tt * EMB], acc);
                    g_ctxT[wp][e * 32 + b] = acc;   // ctx(t), transposed
                }
            }
        } else if (t > 0) {
            // projection(t-1): warp = row, lane = batch
            int pgw = (blockIdx.x - B) * 16 + warp;
            for (int row = pgw; row < NMEL + 1; row += (NBLK - B) * 16) {
                const float* wr; float bias;
                if (row < NMEL) { wr = p.wproj + (size_t)row * (DRNN + EMB); bias = p.bproj[row]; }
                else            { wr = p.wgate;                               bias = p.bgate[0]; }
                const float* dh = g_dhT[rp];    // dh(t-1)
                const float* cx = g_ctxT[rp];   // ctx(t-1)
                float a0 = 0.f, a1 = 0.f, a2 = 0.f, a3 = 0.f;
                const float4* wr4 = (const float4*)wr;
#pragma unroll 4
                for (int k4 = 0; k4 < DRNN / 4; ++k4) {
                    float4 w = wr4[k4];
                    int k = k4 * 4;
                    a0 = fmaf(w.x, dh[(k)     * 32 + lane], a0);
                    a1 = fmaf(w.y, dh[(k + 1) * 32 + lane], a1);
                    a2 = fmaf(w.z, dh[(k + 2) * 32 + lane], a2);
                    a3 = fmaf(w.w, dh[(k + 3) * 32 + lane], a3);
                }
                const float4* wc4 = (const float4*)(wr + DRNN);
#pragma unroll 4
                for (int k4 = 0; k4 < EMB / 4; ++k4) {
                    float4 w = wc4[k4];
                    int k = k4 * 4;
                    a0 = fmaf(w.x, cx[(k)     * 32 + lane], a0);
                    a1 = fmaf(w.y, cx[(k + 1) * 32 + lane], a1);
                    a2 = fmaf(w.z, cx[(k + 2) * 32 + lane], a2);
                    a3 = fmaf(w.w, cx[(k + 3) * 32 + lane], a3);
                }
                float a = a0 + a1 + a2 + a3 + bias;
                if (row < NMEL)
                    p.out[((size_t)lane * NMEL + row) * TOUT + (t - 1)] = a;
                else
                    p.out[GATE_OFF + (size_t)lane * TOUT + (t - 1)] = a;
            }
        }
        grid_sync();
    }
}

// ---------------- launch ----------------
extern "C" void kernel_launch(void* const* d_in, const int* in_sizes, int n_in,
                              void* d_out, int out_size) {
    Params p;
    p.memory     = (const float*)d_in[0];
    p.dec_inputs = (const float*)d_in[1];
    p.mlen       = (const int*)  d_in[2];
    const float* prenet_w1 = (const float*)d_in[3];
    const float* prenet_w2 = (const float*)d_in[4];
    p.att_wih    = (const float*)d_in[5];
    p.att_whh    = (const float*)d_in[6];
    p.att_bih    = (const float*)d_in[7];
    p.att_bhh    = (const float*)d_in[8];
    p.wq         = (const float*)d_in[9];
    const float* wk = (const float*)d_in[10];
    p.conv_w     = (const float*)d_in[11];
    p.conv_b     = (const float*)d_in[12];
    p.wloc       = (const float*)d_in[13];
    p.wv         = (const float*)d_in[14];
    p.dec_wih    = (const float*)d_in[15];
    p.dec_whh    = (const float*)d_in[16];
    p.dec_bih    = (const float*)d_in[17];
    p.dec_bhh    = (const float*)d_in[18];
    p.wproj      = (const float*)d_in[19];
    p.bproj      = (const float*)d_in[20];
    p.wgate      = (const float*)d_in[21];
    p.bgate      = (const float*)d_in[22];
    p.out        = (float*)d_out;

    k_trans_w1<<<(PN * NMEL + 255) / 256, 256>>>(prenet_w1);
    k_trans_w2<<<(PN * PN + 255) / 256, 256>>>(prenet_w2);
    k_trans_wk<<<(AD * EMB + 255) / 256, 256>>>(wk);
    k_quad_att<<<4096, 256>>>(p.att_wih, p.att_whh);
    k_quad_dec<<<4096, 256>>>(p.dec_wih, p.dec_whh);
    k_bias<<<(2 * ARNN + 255) / 256, 256>>>(p.att_bih, p.att_bhh, p.dec_bih, p.dec_bhh);
    k_prenet<<<TOUT, 256>>>(p.dec_inputs);
    k_keys<<<B * (TENC / 8), 128>>>(p.memory);
    k_decoder<<<NBLK, NTHR>>>(p);
}

// round 15
// speedup vs baseline: 1.5648x; 1.4794x over previous
#include <cuda_runtime.h>
#include <math.h>
#include <stdint.h>

#define B     32
#define TENC  256
#define TOUT  400
#define EMB   512
#define NMEL  80
#define PN    256
#define ARNN  1024
#define DRNN  1024
#define AD    128
#define NF    32
#define KSZ   31

#define KA    1792   // att GEMM depth: 256 xs + 512 ctx + 1024 ah
#define KD    2560   // dec GEMM depth: 1024 ah + 512 ctx + 1024 dh

#define NBLK  148
#define NTHR  512

#define CK        256                  // k-chunk
#define NCHUNK    11                   // combined K-space 2816 / 256
#define ACT_FLTS  (CK * B)             // 8192 floats per act buffer
#define WREG_F4   512                  // f4 per weight chunk (2 units x 256 k x 16B)

#define GATE_OFF  ((size_t)B * NMEL * TOUT)
#define ALIGN_OFF (GATE_OFF + (size_t)B * TOUT)

// dynamic smem layout (floats)
#define SM_ACT   0                     // [2][8192]
#define SM_W     (2 * ACT_FLTS)        // [7][2][2048]
#define SM_Q     (SM_W + 7 * 2 * 2048) // 128
#define SM_E     (SM_Q + AD)           // 256
#define SM_SW    (SM_E + TENC)         // 256
#define SM_RED   (SM_SW + TENC)        // 2
#define SM_TOT_F (SM_RED + 2)
#define SMEM_BYTES (SM_TOT_F * 4)      // ~181KB -> 1 block/SM

// ---------------- device scratch ----------------
__device__ __align__(16) float g_xsT[(size_t)TOUT * PN * B];   // [t][k][b]
__device__ __align__(16) float g_keys[(size_t)B * TENC * AD];
__device__ __align__(16) float g_loc[(size_t)B * TENC * AD];
__device__ __align__(16) float g_ahT[2][ARNN * B];   // [u][b]
__device__ __align__(16) float g_ahP[2][B * ARNN];   // [b][u] for q
__device__ __align__(16) float g_acT[ARNN * B];
__device__ __align__(16) float g_dhT[2][DRNN * B];
__device__ __align__(16) float g_dcT[DRNN * B];
__device__ __align__(16) float g_ctxT[2][EMB * B];   // [e][b]
__device__ __align__(16) float g_aw[B * TENC];
__device__ __align__(16) float g_awc[B * TENC];
__device__ __align__(16) float g_wQa[(size_t)ARNN * KA * 4];  // [u][k][g]
__device__ __align__(16) float g_wQd[(size_t)DRNN * KD * 4];
__device__ __align__(16) float g_bqa[ARNN * 4];
__device__ __align__(16) float g_bqd[DRNN * 4];
__device__ __align__(16) float g_w1T[NMEL * PN];
__device__ __align__(16) float g_w2T[PN * PN];
__device__ __align__(16) float g_wkT[EMB * AD];

__device__ unsigned g_cnt = 0;
__device__ volatile unsigned g_gen = 0;

// ---------------- f32x2 helpers ----------------
typedef unsigned long long ull;

__device__ __forceinline__ ull pack2(float x, float y) {
    ull r; asm("mov.b64 %0,{%1,%2};" : "=l"(r) : "f"(x), "f"(y)); return r;
}
__device__ __forceinline__ void fma2(ull& d, ull a, ull b) {
    asm("fma.rn.f32x2 %0,%1,%2,%0;" : "+l"(d) : "l"(a), "l"(b));
}
__device__ __forceinline__ float2 unpack2(ull a) {
    float2 r; asm("mov.b64 {%0,%1},%2;" : "=f"(r.x), "=f"(r.y) : "l"(a)); return r;
}

// ---------------- cp.async helpers ----------------
__device__ __forceinline__ void cpa16(uint32_t dst, const void* src) {
    asm volatile("cp.async.cg.shared.global [%0], [%1], 16;" :: "r"(dst), "l"(src));
}
__device__ __forceinline__ void cpa_commit() { asm volatile("cp.async.commit_group;"); }
__device__ __forceinline__ void cpa_wait0()  { asm volatile("cp.async.wait_group 0;"); }
__device__ __forceinline__ void cpa_wait1()  { asm volatile("cp.async.wait_group 1;"); }

// ---------------- misc helpers ----------------
__device__ __forceinline__ void grid_sync() {
    __syncthreads();
    if (threadIdx.x == 0) {
        __threadfence();
        unsigned gen = g_gen;
        if (atomicAdd(&g_cnt, 1u) == gridDim.x - 1u) {
            g_cnt = 0;
            __threadfence();
            g_gen = gen + 1u;
        } else {
            while (g_gen == gen) { __nanosleep(32); }
            __threadfence();
        }
    }
    __syncthreads();
}

__device__ __forceinline__ float wredsum(float v) {
#pragma unroll
    for (int o = 16; o > 0; o >>= 1) v += __shfl_xor_sync(0xffffffffu, v, o);
    return v;
}

__device__ __forceinline__ float sig_(float x) { return 1.0f / (1.0f + expf(-x)); }

__device__ __forceinline__ float dot4(const float* __restrict__ w,
                                      const float* __restrict__ x,
                                      int n4, float acc, int lane) {
    const float4* w4 = (const float4*)w;
    const float4* x4 = (const float4*)x;
#pragma unroll 4
    for (int i = lane; i < n4; i += 32) {
        float4 a = w4[i];
        float4 b = x4[i];
        acc = fmaf(a.x, b.x, acc);
        acc = fmaf(a.y, b.y, acc);
        acc = fmaf(a.z, b.z, acc);
        acc = fmaf(a.w, b.w, acc);
    }
    return acc;
}

// q GEMV reading cross-SM-written activations via .cg
__device__ __forceinline__ float dot4cg(const float* __restrict__ w,
                                        const float* __restrict__ x,
                                        int n4, int lane) {
    const float4* w4 = (const float4*)w;
    const float4* x4 = (const float4*)x;
    float acc = 0.f;
#pragma unroll 4
    for (int i = lane; i < n4; i += 32) {
        float4 a = w4[i];
        float4 b = __ldcg(x4 + i);
        acc = fmaf(a.x, b.x, acc);
        acc = fmaf(a.y, b.y, acc);
        acc = fmaf(a.z, b.z, acc);
        acc = fmaf(a.w, b.w, acc);
    }
    return acc;
}

// compute one 256-k chunk from smem: 2 units x 4 gates x 32 batch
__device__ __forceinline__ void gemm_chunk(const float* __restrict__ abuf,
                                           const ulonglong2* __restrict__ wbuf,
                                           int lane,
                                           ull& a00, ull& a01, ull& a10, ull& a11) {
#pragma unroll 16
    for (int kk = 0; kk < CK; ++kk) {
        float a = abuf[kk * 32 + lane];
        ull a2 = pack2(a, a);
        ulonglong2 wa = wbuf[kk * 2];
        ulonglong2 wb = wbuf[kk * 2 + 1];
        fma2(a00, wa.x, a2);
        fma2(a01, wa.y, a2);
        fma2(a10, wb.x, a2);
        fma2(a11, wb.y, a2);
    }
}

// stage one weight chunk (2 units x 256 k) into smem via cp.async
__device__ __forceinline__ void stage_w(float* swdst, const float4* wsrc_f4,
                                        int K, int u0, int k0, int lane) {
    uint32_t dbase = (uint32_t)__cvta_generic_to_shared(swdst);
#pragma unroll
    for (int j = 0; j < 16; ++j) {
        int idx = lane + 32 * j;          // 0..511
        int unit = idx >> 8, kk = idx & 255;
        const float4* s = wsrc_f4 + (size_t)(u0 + unit) * K + k0 + kk;
        cpa16(dbase + (uint32_t)(kk * 2 + unit) * 16u, s);
    }
    cpa_commit();
}

// ---------------- params ----------------
struct Params {
    const float* memory;
    const float* dec_inputs;
    const int*   mlen;
    const float* att_wih;  const float* att_whh;
    const float* att_bih;  const float* att_bhh;
    const float* wq;
    const float* conv_w;   const float* conv_b;
    const float* wloc;     const float* wv;
    const float* dec_wih;  const float* dec_whh;
    const float* dec_bih;  const float* dec_bhh;
    const float* wproj;    const float* bproj;
    const float* wgate;    const float* bgate;
    float*       out;
};

// ---------------- pre-kernels ----------------
__global__ void k_trans_w1(const float* __restrict__ w) {
    int i = blockIdx.x * blockDim.x + threadIdx.x;
    if (i < PN * NMEL) { int r = i / NMEL, c = i % NMEL; g_w1T[c * PN + r] = w[i]; }
}
__global__ void k_trans_w2(const float* __restrict__ w) {
    int i = blockIdx.x * blockDim.x + threadIdx.x;
    if (i < PN * PN) { int r = i / PN, c = i % PN; g_w2T[c * PN + r] = w[i]; }
}
__global__ void k_trans_wk(const float* __restrict__ w) {
    int i = blockIdx.x * blockDim.x + threadIdx.x;
    if (i < AD * EMB) { int r = i / EMB, c = i % EMB; g_wkT[c * AD + r] = w[i]; }
}

__global__ void k_quad_att(const float* __restrict__ wih, const float* __restrict__ whh) {
    for (size_t i = blockIdx.x * (size_t)blockDim.x + threadIdx.x;
         i < (size_t)ARNN * KA; i += (size_t)gridDim.x * blockDim.x) {
        int u = (int)(i / KA), k = (int)(i % KA);
        float4 v;
        if (k < PN + EMB) {
            v.x = wih[((size_t)(0 * ARNN + u)) * (PN + EMB) + k];
            v.y = wih[((size_t)(1 * ARNN + u)) * (PN + EMB) + k];
            v.z = wih[((size_t)(2 * ARNN + u)) * (PN + EMB) + k];
            v.w = wih[((size_t)(3 * ARNN + u)) * (PN + EMB) + k];
        } else {
            int kk = k - (PN + EMB);
            v.x = whh[((size_t)(0 * ARNN + u)) * ARNN + kk];
            v.y = whh[((size_t)(1 * ARNN + u)) * ARNN + kk];
            v.z = whh[((size_t)(2 * ARNN + u)) * ARNN + kk];
            v.w = whh[((size_t)(3 * ARNN + u)) * ARNN + kk];
        }
        ((float4*)g_wQa)[i] = v;
    }
}
__global__ void k_quad_dec(const float* __restrict__ wih, const float* __restrict__ whh) {
    for (size_t i = blockIdx.x * (size_t)blockDim.x + threadIdx.x;
         i < (size_t)DRNN * KD; i += (size_t)gridDim.x * blockDim.x) {
        int u = (int)(i / KD), k = (int)(i % KD);
        float4 v;
        if (k < ARNN + EMB) {
            v.x = wih[((size_t)(0 * DRNN + u)) * (ARNN + EMB) + k];
            v.y = wih[((size_t)(1 * DRNN + u)) * (ARNN + EMB) + k];
            v.z = wih[((size_t)(2 * DRNN + u)) * (ARNN + EMB) + k];
            v.w = wih[((size_t)(3 * DRNN + u)) * (ARNN + EMB) + k];
        } else {
            int kk = k - (ARNN + EMB);
            v.x = whh[((size_t)(0 * DRNN + u)) * DRNN + kk];
            v.y = whh[((size_t)(1 * DRNN + u)) * DRNN + kk];
            v.z = whh[((size_t)(2 * DRNN + u)) * DRNN + kk];
            v.w = whh[((size_t)(3 * DRNN + u)) * DRNN + kk];
        }
        ((float4*)g_wQd)[i] = v;
    }
}
__global__ void k_bias(const float* abih, const float* abhh,
                       const float* dbih, const float* dbhh) {
    int i = blockIdx.x * blockDim.x + threadIdx.x;
    if (i < ARNN) {
#pragma unroll
        for (int g = 0; g < 4; ++g)
            g_bqa[i * 4 + g] = abih[g * ARNN + i] + abhh[g * ARNN + i];
    } else if (i < 2 * ARNN) {
        int u = i - ARNN;
#pragma unroll
        for (int g = 0; g < 4; ++g)
            g_bqd[u * 4 + g] = dbih[g * DRNN + u] + dbhh[g * DRNN + u];
    }
}

__global__ __launch_bounds__(256) void k_prenet(const float* __restrict__ dec_inputs) {
    __shared__ float sin_[B][NMEL];
    __shared__ float sh1[B][PN];
    int t = blockIdx.x;
    int tid = threadIdx.x;
    for (int i = tid; i < B * NMEL; i += 256) {
        int b = i / NMEL, k = i % NMEL;
        sin_[b][k] = (t == 0) ? 0.0f
                   : dec_inputs[((size_t)b * TOUT + (t - 1)) * NMEL + k];
    }
    __syncthreads();
    int m = tid;
    float acc[B];
#pragma unroll
    for (int b = 0; b < B; ++b) acc[b] = 0.0f;
    for (int k = 0; k < NMEL; ++k) {
        float wv_ = g_w1T[k * PN + m];
#pragma unroll
        for (int b = 0; b < B; ++b) acc[b] = fmaf(wv_, sin_[b][k], acc[b]);
    }
#pragma unroll
    for (int b = 0; b < B; ++b) sh1[b][m] = fmaxf(acc[b], 0.0f);
    __syncthreads();
#pragma unroll
    for (int b = 0; b < B; ++b) acc[b] = 0.0f;
    for (int k = 0; k < PN; ++k) {
        float wv_ = g_w2T[k * PN + m];
#pragma unroll
        for (int b = 0; b < B; ++b) acc[b] = fmaf(wv_, sh1[b][k], acc[b]);
    }
#pragma unroll
    for (int b = 0; b < B; ++b)
        g_xsT[((size_t)t * PN + m) * B + b] = fmaxf(acc[b], 0.0f);
}

__global__ __launch_bounds__(128) void k_keys(const float* __restrict__ memory) {
    __shared__ float sm[8][EMB];
    int b  = blockIdx.x >> 5;
    int t0 = (blockIdx.x & 31) * 8;
    int tid = threadIdx.x;
    for (int i = tid; i < 8 * EMB; i += 128) {
        int j = i >> 9, k = i & 511;
        sm[j][k] = memory[((size_t)b * TENC + t0 + j) * EMB + k];
    }
    __syncthreads();
    int d = tid;
    float acc[8];
#pragma unroll
    for (int j = 0; j < 8; ++j) acc[j] = 0.0f;
    for (int k = 0; k < EMB; ++k) {
        float wv_ = g_wkT[k * AD + d];
#pragma unroll
        for (int j = 0; j < 8; ++j) acc[j] = fmaf(wv_, sm[j][k], acc[j]);
    }
#pragma unroll
    for (int j = 0; j < 8; ++j)
        g_keys[((size_t)b * TENC + t0 + j) * AD + d] = acc[j];
}

// chunk c -> act source pointer (combined K-space [xs|ctx|ah|dh])
__device__ __forceinline__ const float* act_src(int c, int t, int rp, int wp) {
    if (c == 0)  return g_xsT + (size_t)(t < TOUT ? t : TOUT - 1) * PN * B;
    if (c <= 2)  return g_ctxT[rp] + (c - 1) * CK * B;
    if (c <= 6)  return g_ahT[rp] + (c - 3) * CK * B;
    return g_dhT[wp] + (c - 7) * CK * B;
}
// chunk c -> weight k0 in each network's own K-order
__device__ __forceinline__ int att_k0(int c) { return c * CK; }  // [xs|ctx|ah] matches
__device__ __forceinline__ int dec_k0(int c) {
    // dec weight order: [ah 0..1023 | ctx 1024..1535 | dh 1536..2559]
    if (c < 3) return 1024 + (c - 1) * CK;   // ctx chunks
    if (c < 7) return (c - 3) * CK;          // ah chunks
    return 1536 + (c - 7) * CK;              // dh chunks
}

// ---------------- persistent decoder ----------------
__global__ __launch_bounds__(NTHR) void k_decoder(Params p) {
    extern __shared__ float sm_[];
    float* s_act = sm_ + SM_ACT;
    float* s_w   = sm_ + SM_W;
    float* s_q   = sm_ + SM_Q;
    float* s_e   = sm_ + SM_E;
    float* s_sw  = sm_ + SM_SW;
    float* s_red = sm_ + SM_RED;

    const int tid  = threadIdx.x;
    const int lane = tid & 31;
    const int warp = tid >> 5;

    // GEMM task mapping: interleave att/dec across SMSPs
    const int  gid    = warp * NBLK + blockIdx.x;        // warp<7
    const bool isComp = (warp < 7) && (gid < 1024);
    const bool isAtt  = isComp && (gid < 512);
    const int  u0     = isAtt ? gid * 2 : (gid - 512) * 2;
    const int  c_lo   = isAtt ? 0 : 1;
    const int  c_hi   = isAtt ? 7 : 11;
    const float4* wsrc = isAtt ? (const float4*)g_wQa : (const float4*)g_wQd;
    const int  KW     = isAtt ? KA : KD;
    float* s_wme = s_w + warp * (2 * 2048);

    // ---- zero-init state ----
    {
        const int tot = blockDim.x * gridDim.x;
        const int gt  = blockIdx.x * blockDim.x + tid;
        for (int i = gt; i < 2 * ARNN * B; i += tot) { g_ahT[0][i] = 0.f; g_ahP[0][i] = 0.f; }
        for (int i = gt; i < 2 * DRNN * B; i += tot) g_dhT[0][i] = 0.f;
        for (int i = gt; i < 2 * EMB * B; i += tot) g_ctxT[0][i] = 0.f;
        for (int i = gt; i < ARNN * B; i += tot) g_acT[i] = 0.f;
        for (int i = gt; i < DRNN * B; i += tot) g_dcT[i] = 0.f;
        for (int i = gt; i < B * TENC; i += tot) { g_aw[i] = 0.f; g_awc[i] = 0.f; }
    }
    grid_sync();

    for (int t = 0; t <= TOUT; ++t) {
        const int rp = (t + 1) & 1;
        const int wp = t & 1;
        const bool active = isComp && (isAtt ? (t < TOUT) : (t > 0));

        // ================= Phase A: chunked smem GEMM =================
        ull a00 = 0, a01 = 0, a10 = 0, a11 = 0;

        // prologue: stage act chunk 0 (loaders) + first weight chunk (compute)
        if (warp >= 7) {
            const float4* src = (const float4*)act_src(0, t, rp, wp);
            uint32_t dbase = (uint32_t)__cvta_generic_to_shared(s_act);
            int idx0 = tid - 224;                        // 0..287
            for (int i = idx0; i < ACT_FLTS / 4; i += 288)
                cpa16(dbase + (uint32_t)i * 16u, src + i);
            cpa_commit();
            cpa_wait0();
        } else if (active) {
            stage_w(s_wme + (c_lo & 1) * 2048, wsrc, KW, u0,
                    isAtt ? att_k0(c_lo) : dec_k0(c_lo), lane);
        }
        __syncthreads();

        for (int c = 0; c < NCHUNK; ++c) {
            if (warp < 7) {
                if (active && c >= c_lo && c < c_hi) {
                    bool more = (c + 1 < c_hi);
                    if (more)
                        stage_w(s_wme + ((c + 1) & 1) * 2048, wsrc, KW, u0,
                                isAtt ? att_k0(c + 1) : dec_k0(c + 1), lane);
                    if (more) cpa_wait1(); else cpa_wait0();
                    gemm_chunk(s_act + (c & 1) * ACT_FLTS,
                               (const ulonglong2*)(s_wme + (c & 1) * 2048),
                               lane, a00, a01, a10, a11);
                    if (c == c_hi - 1) {
                        // finalize LSTM pointwise
                        const float* bq = isAtt ? g_bqa : g_bqd;
                        float* cst = isAtt ? g_acT : g_dcT;
#pragma unroll
                        for (int j = 0; j < 2; ++j) {
                            int u = u0 + j;
                            float2 g01 = unpack2(j ? a10 : a00);
                            float2 g23 = unpack2(j ? a11 : a01);
                            float4 bb = ((const float4*)bq)[u];
                            float i_ = g01.x + bb.x, f_ = g01.y + bb.y;
                            float gg = g23.x + bb.z, oo = g23.y + bb.w;
                            float cc = cst[u * 32 + lane];
                            float c2 = sig_(f_) * cc + sig_(i_) * tanhf(gg);
                            cst[u * 32 + lane] = c2;
                            float h = sig_(oo) * tanhf(c2);
                            if (isAtt) {
                                g_ahT[wp][u * 32 + lane] = h;
                                g_ahP[wp][lane * ARNN + u] = h;
                            } else {
                                g_dhT[rp][u * 32 + lane] = h;
                            }
                        }
                    }
                }
            } else {
                // loaders: stage act chunk c+1, then conv on first iteration
                if (c + 1 < NCHUNK) {
                    const float4* src = (const float4*)act_src(c + 1, t, rp, wp);
                    uint32_t dbase = (uint32_t)__cvta_generic_to_shared(
                        s_act + ((c + 1) & 1) * ACT_FLTS);
                    int idx0 = tid - 224;
                    for (int i = idx0; i < ACT_FLTS / 4; i += 288)
                        cpa16(dbase + (uint32_t)i * 16u, src + i);
                }
                cpa_commit();
                if (c == 0 && t < TOUT) {
                    // location conv + wloc projection (overlap cp.async latency)
                    for (int cid = blockIdx.x * 9 + (warp - 7); cid < B * TENC; cid += NBLK * 9) {
                        int b = cid >> 8, tt = cid & 255;
                        const float* cw0 = p.conv_w + lane * (2 * KSZ);
                        float cv = p.conv_b[lane];
#pragma unroll
                        for (int k = 0; k < KSZ; ++k) {
                            int pp = tt + k - 15;
                            if (pp >= 0 && pp < TENC) {
                                cv = fmaf(cw0[k],       __ldcg(&g_aw[b * TENC + pp]), cv);
                                cv = fmaf(cw0[KSZ + k], __ldcg(&g_awc[b * TENC + pp]), cv);
                            }
                        }
                        float a0 = 0.f, a1 = 0.f, a2 = 0.f, a3 = 0.f;
#pragma unroll
                        for (int src_ = 0; src_ < 32; ++src_) {
                            float v = __shfl_sync(0xffffffffu, cv, src_);
                            a0 = fmaf(v, p.wloc[(lane)      * NF + src_], a0);
                            a1 = fmaf(v, p.wloc[(lane + 32) * NF + src_], a1);
                            a2 = fmaf(v, p.wloc[(lane + 64) * NF + src_], a2);
                            a3 = fmaf(v, p.wloc[(lane + 96) * NF + src_], a3);
                        }
                        size_t o = ((size_t)b * TENC + tt) * AD;
                        g_loc[o + lane]      = a0;
                        g_loc[o + lane + 32] = a1;
                        g_loc[o + lane + 64] = a2;
                        g_loc[o + lane + 96] = a3;
                    }
                }
                cpa_wait0();
            }
            __syncthreads();
        }
        grid_sync();

        // ================= Phase B =================
        if (blockIdx.x < B) {
            if (t < TOUT) {
                const int b = blockIdx.x;
                const float* hrow = g_ahP[wp] + b * ARNN;   // ah(t), cross-SM
#pragma unroll
                for (int j = 0; j < 8; ++j) {
                    int d = warp * 8 + j;
                    float a = dot4cg(p.wq + (size_t)d * ARNN, hrow, ARNN / 4, lane);
                    a = wredsum(a);
                    if (lane == 0) s_q[d] = a;
                }
                __syncthreads();
                const int len = p.mlen[b];
#pragma unroll
                for (int j = 0; j < 16; ++j) {
                    int tt = warp + j * 16;
                    size_t o = ((size_t)b * TENC + tt) * AD;
                    float a = 0.f;
#pragma unroll
                    for (int jj = 0; jj < 4; ++jj) {
                        int d = lane + jj * 32;
                        float s = s_q[d] + g_keys[o + d] + __ldcg(&g_loc[o + d]);
                        a = fmaf(p.wv[d], tanhf(s), a);
                    }
                    a = wredsum(a);
                    if (lane == 0) s_e[tt] = (tt >= len) ? -1e9f : a;
                }
                __syncthreads();
                if (warp == 0) {
                    float m = -3.4e38f;
#pragma unroll
                    for (int j = 0; j < 8; ++j) m = fmaxf(m, s_e[lane + j * 32]);
#pragma unroll
                    for (int o = 16; o > 0; o >>= 1)
                        m = fmaxf(m, __shfl_xor_sync(0xffffffffu, m, o));
                    float s = 0.f;
#pragma unroll
                    for (int j = 0; j < 8; ++j) s += expf(s_e[lane + j * 32] - m);
                    s = wredsum(s);
                    if (lane == 0) { s_red[0] = m; s_red[1] = 1.0f / s; }
                }
                __syncthreads();
                if (tid < TENC) {
                    float w = expf(s_e[tid] - s_red[0]) * s_red[1];
                    s_sw[tid] = w;
                    g_aw[b * TENC + tid] = w;
                    g_awc[b * TENC + tid] += w;
                    p.out[ALIGN_OFF + ((size_t)b * TOUT + t) * TENC + tid] = w;
                }
                __syncthreads();
                {
                    int e = warp * 32 + lane;
                    const float* mb = p.memory + (size_t)b * TENC * EMB + e;
                    float acc = 0.f;
#pragma unroll 8
                    for (int tt = 0; tt < TENC; ++tt)
                        acc = fmaf(s_sw[tt], mb[(size_t)tt * EMB], acc);
                    g_ctxT[wp][e * 32 + b] = acc;
                }
            }
        } else if (t > 0) {
            // projection(t-1): warp = row, lane = batch
            int pgw = (blockIdx.x - B) * 16 + warp;
            for (int row = pgw; row < NMEL + 1; row += (NBLK - B) * 16) {
                const float* wr; float bias;
                if (row < NMEL) { wr = p.wproj + (size_t)row * (DRNN + EMB); bias = p.bproj[row]; }
                else            { wr = p.wgate;                               bias = p.bgate[0]; }
                const float* dh = g_dhT[rp];
                const float* cx = g_ctxT[rp];
                float a0 = 0.f, a1 = 0.f, a2 = 0.f, a3 = 0.f;
                const float4* wr4 = (const float4*)wr;
#pragma unroll 4
                for (int k4 = 0; k4 < DRNN / 4; ++k4) {
                    float4 w = wr4[k4];
                    int k = k4 * 4;
                    a0 = fmaf(w.x, __ldcg(&dh[(k)     * 32 + lane]), a0);
                    a1 = fmaf(w.y, __ldcg(&dh[(k + 1) * 32 + lane]), a1);
                    a2 = fmaf(w.z, __ldcg(&dh[(k + 2) * 32 + lane]), a2);
                    a3 = fmaf(w.w, __ldcg(&dh[(k + 3) * 32 + lane]), a3);
                }
                const float4* wc4 = (const float4*)(wr + DRNN);
#pragma unroll 4
                for (int k4 = 0; k4 < EMB / 4; ++k4) {
                    float4 w = wc4[k4];
                    int k = k4 * 4;
                    a0 = fmaf(w.x, __ldcg(&cx[(k)     * 32 + lane]), a0);
                    a1 = fmaf(w.y, __ldcg(&cx[(k + 1) * 32 + lane]), a1);
                    a2 = fmaf(w.z, __ldcg(&cx[(k + 2) * 32 + lane]), a2);
                    a3 = fmaf(w.w, __ldcg(&cx[(k + 3) * 32 + lane]), a3);
                }
                float a = a0 + a1 + a2 + a3 + bias;
                if (row < NMEL)
                    p.out[((size_t)lane * NMEL + row) * TOUT + (t - 1)] = a;
                else
                    p.out[GATE_OFF + (size_t)lane * TOUT + (t - 1)] = a;
            }
        }
        grid_sync();
    }
}

// ---------------- launch ----------------
extern "C" void kernel_launch(void* const* d_in, const int* in_sizes, int n_in,
                              void* d_out, int out_size) {
    Params p;
    p.memory     = (const float*)d_in[0];
    p.dec_inputs = (const float*)d_in[1];
    p.mlen       = (const int*)  d_in[2];
    const float* prenet_w1 = (const float*)d_in[3];
    const float* prenet_w2 = (const float*)d_in[4];
    p.att_wih    = (const float*)d_in[5];
    p.att_whh    = (const float*)d_in[6];
    p.att_bih    = (const float*)d_in[7];
    p.att_bhh    = (const float*)d_in[8];
    p.wq         = (const float*)d_in[9];
    const float* wk = (const float*)d_in[10];
    p.conv_w     = (const float*)d_in[11];
    p.conv_b     = (const float*)d_in[12];
    p.wloc       = (const float*)d_in[13];
    p.wv         = (const float*)d_in[14];
    p.dec_wih    = (const float*)d_in[15];
    p.dec_whh    = (const float*)d_in[16];
    p.dec_bih    = (const float*)d_in[17];
    p.dec_bhh    = (const float*)d_in[18];
    p.wproj      = (const float*)d_in[19];
    p.bproj      = (const float*)d_in[20];
    p.wgate      = (const float*)d_in[21];
    p.bgate      = (const float*)d_in[22];
    p.out        = (float*)d_out;

    static int smem_set = 0;
    if (!smem_set) {
        cudaFuncSetAttribute(k_decoder, cudaFuncAttributeMaxDynamicSharedMemorySize,
                             SMEM_BYTES);
        smem_set = 1;
    }

    k_trans_w1<<<(PN * NMEL + 255) / 256, 256>>>(prenet_w1);
    k_trans_w2<<<(PN * PN + 255) / 256, 256>>>(prenet_w2);
    k_trans_wk<<<(AD * EMB + 255) / 256, 256>>>(wk);
    k_quad_att<<<4096, 256>>>(p.att_wih, p.att_whh);
    k_quad_dec<<<4096, 256>>>(p.dec_wih, p.dec_whh);
    k_bias<<<(2 * ARNN + 255) / 256, 256>>>(p.att_bih, p.att_bhh, p.dec_bih, p.dec_bhh);
    k_prenet<<<TOUT, 256>>>(p.dec_inputs);
    k_keys<<<B * (TENC / 8), 128>>>(p.memory);
    k_decoder<<<NBLK, NTHR, SMEM_BYTES>>>(p);
}